// round 11
// baseline (speedup 1.0000x reference)
#include <cuda_runtime.h>
#include <cuda_bf16.h>
#include <cuda_fp16.h>

// Problem constants
#define BATCH 4
#define SEQ   2048
#define EMBD  1024
#define NHEAD 16
#define HDIM  64
#define QKV_N (3*EMBD)

// ---------------------------------------------------------------------------
// Scratch (device globals: allocation-free, graph-capture safe)
// ---------------------------------------------------------------------------
__device__ __align__(256) __half g_xf[(size_t)BATCH * SEQ * EMBD];
__device__ __align__(256) __half g_wqf[(size_t)EMBD * QKV_N];
__device__ __align__(256) __half g_wof[(size_t)EMBD * EMBD];
__device__ __align__(256) __half g_qkvf[(size_t)BATCH * SEQ * QKV_N];
__device__ __align__(256) __half g_af[(size_t)BATCH * SEQ * EMBD];

// ---------------------------------------------------------------------------
// Common PTX helpers
// ---------------------------------------------------------------------------
__device__ __forceinline__ unsigned sptr(const void* p) {
    return (unsigned)__cvta_generic_to_shared(p);
}
__device__ __forceinline__ void cpa16(unsigned s, const void* g) {
    asm volatile("cp.async.cg.shared.global [%0], [%1], 16;\n" :: "r"(s), "l"(g));
}
__device__ __forceinline__ void ldsm4(unsigned* r, unsigned a) {
    asm volatile("ldmatrix.sync.aligned.m8n8.x4.shared.b16 {%0,%1,%2,%3},[%4];"
                 : "=r"(r[0]), "=r"(r[1]), "=r"(r[2]), "=r"(r[3]) : "r"(a));
}
__device__ __forceinline__ void ldsm4t(unsigned* r, unsigned a) {
    asm volatile("ldmatrix.sync.aligned.m8n8.x4.trans.shared.b16 {%0,%1,%2,%3},[%4];"
                 : "=r"(r[0]), "=r"(r[1]), "=r"(r[2]), "=r"(r[3]) : "r"(a));
}
__device__ __forceinline__ void mma16816h(float* d, const unsigned* a, const unsigned* b) {
    asm volatile(
        "mma.sync.aligned.m16n8k16.row.col.f32.f16.f16.f32 "
        "{%0,%1,%2,%3},{%4,%5,%6,%7},{%8,%9},{%0,%1,%2,%3};"
        : "+f"(d[0]), "+f"(d[1]), "+f"(d[2]), "+f"(d[3])
        : "r"(a[0]), "r"(a[1]), "r"(a[2]), "r"(a[3]), "r"(b[0]), "r"(b[1]));
}
__device__ __forceinline__ unsigned packh2(float a, float b) {
    __half2 hv = __floats2half2_rn(a, b);
    return *(unsigned*)&hv;
}

// ---------------------------------------------------------------------------
// fp32 -> fp16 convert, vectorized x4
// ---------------------------------------------------------------------------
__global__ __launch_bounds__(256) void tofp16x4(
    const float4* __restrict__ in, uint2* __restrict__ out, int n4)
{
    int i = blockIdx.x * blockDim.x + threadIdx.x;
    if (i >= n4) return;
    float4 v = in[i];
    uint2 o;
    o.x = packh2(v.x, v.y);
    o.y = packh2(v.z, v.w);
    out[i] = o;
}

// ---------------------------------------------------------------------------
// Tensor-core fp16 GEMM: C[M,N] = A[M,K] @ B[K,N] + bias, fp32 accumulate.
// 128 threads, 4 warps, warp tile 64x64, CTA tile 128x128, GBK=64, 2 CTAs/SM.
// OMODE 0: write fp32 C.   OMODE 2: write fp16 C.
// ---------------------------------------------------------------------------
#define GBM 128
#define GBN 128
#define GBK 64
#define APITCH 72                  // 64 + 8 pad (halves)
#define BPITCH 136                 // 128 + 8 pad (halves)
#define ASZ (128*APITCH)           // 9216 halves
#define BSZ (64*BPITCH)            // 8704 halves
#define GEMM_SMEM ((2*ASZ + 2*BSZ) * 2)   // 71680 bytes

template<int OMODE>
__global__ __launch_bounds__(128, 2) void gemm_f16(
    const __half* __restrict__ A, const __half* __restrict__ B,
    const float* __restrict__ bias,
    float* __restrict__ C, __half* __restrict__ Cf,
    int M, int N, int K)
{
    extern __shared__ char smem[];
    __half* sA = (__half*)smem;
    __half* sB = sA + 2 * ASZ;

    const int tid  = threadIdx.x;
    const int lane = tid & 31;
    const int warp = tid >> 5;
    const int bm   = blockIdx.y * GBM;
    const int bn   = blockIdx.x * GBN;
    const int wm   = (warp & 1) * 64;
    const int wn   = (warp >> 1) * 64;

    float acc[4][8][4];
#pragma unroll
    for (int mi = 0; mi < 4; mi++)
#pragma unroll
        for (int n = 0; n < 8; n++)
#pragma unroll
            for (int e = 0; e < 4; e++) acc[mi][n][e] = 0.f;

    auto prefetch = [&](int st, int k0) {
        const __half* a = A + (size_t)bm * K + k0;
#pragma unroll
        for (int i = 0; i < 8; i++) {
            int idx = tid + i * 128;            // 0..1023
            int r = idx >> 3, c = (idx & 7) * 8;
            cpa16(sptr(&sA[st * ASZ + r * APITCH + c]), a + (size_t)r * K + c);
        }
        const __half* b = B + (size_t)k0 * N + bn;
#pragma unroll
        for (int i = 0; i < 8; i++) {
            int idx = tid + i * 128;
            int r = idx >> 4, c = (idx & 15) * 8;
            cpa16(sptr(&sB[st * BSZ + r * BPITCH + c]), b + (size_t)r * N + c);
        }
        asm volatile("cp.async.commit_group;");
    };

    const int NIT = K / GBK;
    prefetch(0, 0);
    for (int it = 0; it < NIT; it++) {
        if (it + 1 < NIT) {
            prefetch((it + 1) & 1, (it + 1) * GBK);
            asm volatile("cp.async.wait_group 1;");
        } else {
            asm volatile("cp.async.wait_group 0;");
        }
        __syncthreads();
        const int st = it & 1;

#pragma unroll
        for (int kk = 0; kk < GBK; kk += 16) {
            unsigned af[4][4], bf[4][4];
#pragma unroll
            for (int mi = 0; mi < 4; mi++) {
                int row = wm + mi * 16 + (lane & 15);
                int col = kk + (lane >> 4) * 8;
                ldsm4(af[mi], sptr(&sA[st * ASZ + row * APITCH + col]));
            }
#pragma unroll
            for (int nj = 0; nj < 4; nj++) {
                int row = kk + (lane & 15);
                int col = wn + nj * 16 + (lane >> 4) * 8;
                ldsm4t(bf[nj], sptr(&sB[st * BSZ + row * BPITCH + col]));
            }
#pragma unroll
            for (int mi = 0; mi < 4; mi++)
#pragma unroll
                for (int nj = 0; nj < 4; nj++)
#pragma unroll
                    for (int sub = 0; sub < 2; sub++)
                        mma16816h(acc[mi][nj * 2 + sub], af[mi], &bf[nj][sub * 2]);
        }
        __syncthreads();
    }

#pragma unroll
    for (int mi = 0; mi < 4; mi++) {
        int r0 = bm + wm + mi * 16 + (lane >> 2);
#pragma unroll
        for (int n = 0; n < 8; n++) {
            int c0 = bn + wn + n * 8 + (lane & 3) * 2;
            float2 bv = *(const float2*)(bias + c0);
            float v00 = acc[mi][n][0] + bv.x, v01 = acc[mi][n][1] + bv.y;
            float v10 = acc[mi][n][2] + bv.x, v11 = acc[mi][n][3] + bv.y;
            if (OMODE == 0) {
                *(float2*)(C + (size_t)r0 * N + c0) = make_float2(v00, v01);
                *(float2*)(C + (size_t)(r0 + 8) * N + c0) = make_float2(v10, v11);
            } else {
                *(unsigned*)(Cf + (size_t)r0 * N + c0) = packh2(v00, v01);
                *(unsigned*)(Cf + (size_t)(r0 + 8) * N + c0) = packh2(v10, v11);
            }
        }
    }
}

// ---------------------------------------------------------------------------
// Tensor-core causal flash attention, single fp16 MMA path.
// Softmax in log2 domain: scores scaled by 0.125*log2(e), exp2f throughout.
// ---------------------------------------------------------------------------
#define KPH 72
#define TSZH (64*KPH)              // halves per tile
#define STGH (2*TSZH)              // K, V
#define FLASH_SMEM (2*STGH*2)      // bytes (36864)
#define SCALE_L2E 0.1803368801f    // 0.125 * log2(e)

__global__ __launch_bounds__(256, 2) void flash_attn_mma(
    const __half* __restrict__ qkv, __half* __restrict__ outf)
{
    extern __shared__ char smraw[];
    __half* sm = (__half*)smraw;

    const int tid  = threadIdx.x;
    const int lane = tid & 31;
    const int warp = tid >> 5;
    const int bh   = blockIdx.y;
    const int b    = bh >> 4;
    const int h    = bh & (NHEAD - 1);
    const int qb   = (gridDim.x - 1) - blockIdx.x;  // heavy tiles first
    const int q0   = qb * 128;
    const int wm   = warp * 16;
    const int r    = lane >> 2;
    const int cp   = (lane & 3) * 2;
    const int qrow = q0 + wm + r;

    // ---- Q fragments straight from global (packed half2 = one u32) ----
    unsigned qf[4][4];
    {
        const size_t base  = ((size_t)(b * SEQ) + qrow) * QKV_N + h * HDIM;
        const size_t base8 = base + (size_t)8 * QKV_N;
#pragma unroll
        for (int kk = 0; kk < 4; kk++) {
            int c0 = kk * 16 + cp;
            qf[kk][0] = *(const unsigned*)(qkv + base  + c0);
            qf[kk][1] = *(const unsigned*)(qkv + base8 + c0);
            qf[kk][2] = *(const unsigned*)(qkv + base  + c0 + 8);
            qf[kk][3] = *(const unsigned*)(qkv + base8 + c0 + 8);
        }
    }

    float m0 = -1e30f, m1 = -1e30f, l0 = 0.f, l1 = 0.f;
    float o[8][4];
#pragma unroll
    for (int nf = 0; nf < 8; nf++)
#pragma unroll
        for (int e = 0; e < 4; e++) o[nf][e] = 0.f;

    const size_t koff = (size_t)EMBD + h * HDIM;
    const size_t voff = (size_t)(2 * EMBD) + h * HDIM;

    auto prefetch = [&](int st, int k0) {
#pragma unroll
        for (int i = 0; i < 4; i++) {
            int id = tid + i * 256;           // 0..1023
            int t  = id >> 9;                 // 0:K 1:V
            int rr = (id >> 3) & 63;
            int cc = (id & 7) * 8;
            const __half* src = qkv + ((size_t)(b * SEQ) + k0 + rr) * QKV_N
                              + (t ? voff : koff) + cc;
            cpa16(sptr(&sm[st * STGH + t * TSZH + rr * KPH + cc]), src);
        }
        asm volatile("cp.async.commit_group;");
    };

    const int ntiles = 2 * qb + 2;
    prefetch(0, 0);
    for (int t = 0; t < ntiles; t++) {
        const int k0 = t * 64;
        if (t + 1 < ntiles) {
            prefetch((t + 1) & 1, (t + 1) * 64);
            asm volatile("cp.async.wait_group 1;");
        } else {
            asm volatile("cp.async.wait_group 0;");
        }
        __syncthreads();
        const int st = t & 1;

        if (k0 <= q0 + wm + 15) {   // causal warp-level skip
            const __half* Kf = sm + st * STGH;
            const __half* Vf = sm + st * STGH + TSZH;

            // ---- S = Q K^T ----
            float s[8][4];
#pragma unroll
            for (int nf = 0; nf < 8; nf++)
#pragma unroll
                for (int e = 0; e < 4; e++) s[nf][e] = 0.f;

#pragma unroll
            for (int kk = 0; kk < 4; kk++) {
#pragma unroll
                for (int g = 0; g < 4; g++) {
                    unsigned kf4[4];
                    int off = (16 * g + (lane & 15)) * KPH + kk * 16 + (lane >> 4) * 8;
                    ldsm4(kf4, sptr(Kf + off));
                    unsigned b0[2] = {kf4[0], kf4[2]}, b1[2] = {kf4[1], kf4[3]};
                    mma16816h(s[2*g],     qf[kk], b0);
                    mma16816h(s[2*g + 1], qf[kk], b1);
                }
            }

            // ---- masking + online softmax (log2 domain) ----
            const bool need_mask = (k0 + 63) > (q0 + wm);
            float mx0 = -1e30f, mx1 = -1e30f;
#pragma unroll
            for (int nf = 0; nf < 8; nf++) {
#pragma unroll
                for (int e = 0; e < 4; e++) s[nf][e] *= SCALE_L2E;
                if (need_mask) {
                    int c0 = k0 + nf * 8 + cp;
                    if (c0     > qrow)     s[nf][0] = -1e30f;
                    if (c0 + 1 > qrow)     s[nf][1] = -1e30f;
                    if (c0     > qrow + 8) s[nf][2] = -1e30f;
                    if (c0 + 1 > qrow + 8) s[nf][3] = -1e30f;
                }
                mx0 = fmaxf(mx0, fmaxf(s[nf][0], s[nf][1]));
                mx1 = fmaxf(mx1, fmaxf(s[nf][2], s[nf][3]));
            }
            mx0 = fmaxf(mx0, __shfl_xor_sync(0xffffffffu, mx0, 1));
            mx0 = fmaxf(mx0, __shfl_xor_sync(0xffffffffu, mx0, 2));
            mx1 = fmaxf(mx1, __shfl_xor_sync(0xffffffffu, mx1, 1));
            mx1 = fmaxf(mx1, __shfl_xor_sync(0xffffffffu, mx1, 2));

            const float nm0 = fmaxf(m0, mx0), nm1 = fmaxf(m1, mx1);
            const float cr0 = exp2f(m0 - nm0), cr1 = exp2f(m1 - nm1);
            m0 = nm0; m1 = nm1;
            l0 *= cr0; l1 *= cr1;
#pragma unroll
            for (int nf = 0; nf < 8; nf++) {
                o[nf][0] *= cr0; o[nf][1] *= cr0;
                o[nf][2] *= cr1; o[nf][3] *= cr1;
            }

            unsigned pf[8][2];
#pragma unroll
            for (int nf = 0; nf < 8; nf++) {
                float p0 = exp2f(s[nf][0] - m0);
                float p1 = exp2f(s[nf][1] - m0);
                float p2 = exp2f(s[nf][2] - m1);
                float p3 = exp2f(s[nf][3] - m1);
                l0 += p0 + p1;
                l1 += p2 + p3;
                pf[nf][0] = packh2(p0, p1);
                pf[nf][1] = packh2(p2, p3);
            }

            // ---- O += P V ----
#pragma unroll
            for (int kp = 0; kp < 4; kp++) {
                unsigned pa[4] = {pf[2*kp][0], pf[2*kp][1], pf[2*kp+1][0], pf[2*kp+1][1]};
#pragma unroll
                for (int dg = 0; dg < 4; dg++) {
                    unsigned vf4[4];
                    int off = (kp * 16 + (lane & 15)) * KPH + dg * 16 + (lane >> 4) * 8;
                    ldsm4t(vf4, sptr(Vf + off));
                    mma16816h(o[2*dg],     pa, &vf4[0]);
                    mma16816h(o[2*dg + 1], pa, &vf4[2]);
                }
            }
        }
        __syncthreads();
    }

    // ---- finalize: quad-reduce l, normalize, store fp16 ----
    l0 += __shfl_xor_sync(0xffffffffu, l0, 1);
    l0 += __shfl_xor_sync(0xffffffffu, l0, 2);
    l1 += __shfl_xor_sync(0xffffffffu, l1, 1);
    l1 += __shfl_xor_sync(0xffffffffu, l1, 2);
    const float inv0 = 1.f / l0, inv1 = 1.f / l1;

    const size_t obase  = ((size_t)(b * SEQ) + qrow) * EMBD + h * HDIM;
    const size_t obase8 = obase + (size_t)8 * EMBD;
#pragma unroll
    for (int nf = 0; nf < 8; nf++) {
        int c0 = nf * 8 + cp;
        *(unsigned*)(outf + obase  + c0) = packh2(o[nf][0] * inv0, o[nf][1] * inv0);
        *(unsigned*)(outf + obase8 + c0) = packh2(o[nf][2] * inv1, o[nf][3] * inv1);
    }
}

// ---------------------------------------------------------------------------
// Launch
// ---------------------------------------------------------------------------
extern "C" void kernel_launch(void* const* d_in, const int* in_sizes, int n_in,
                              void* d_out, int out_size)
{
    const float* x     = (const float*)d_in[0];
    const float* W_qkv = (const float*)d_in[1];
    const float* b_qkv = (const float*)d_in[2];
    const float* W_out = (const float*)d_in[3];
    const float* b_out = (const float*)d_in[4];
    float* out = (float*)d_out;

    __half *xf, *wqf, *wof, *qkvf, *af;
    cudaGetSymbolAddress((void**)&xf,   g_xf);
    cudaGetSymbolAddress((void**)&wqf,  g_wqf);
    cudaGetSymbolAddress((void**)&wof,  g_wof);
    cudaGetSymbolAddress((void**)&qkvf, g_qkvf);
    cudaGetSymbolAddress((void**)&af,   g_af);

    const int M = BATCH * SEQ;                       // 8192

    cudaFuncSetAttribute(gemm_f16<0>, cudaFuncAttributeMaxDynamicSharedMemorySize, GEMM_SMEM);
    cudaFuncSetAttribute(gemm_f16<2>, cudaFuncAttributeMaxDynamicSharedMemorySize, GEMM_SMEM);
    cudaFuncSetAttribute(flash_attn_mma, cudaFuncAttributeMaxDynamicSharedMemorySize, FLASH_SMEM);

    // 1) convert inputs to fp16
    {
        int n4 = M * EMBD / 4;
        tofp16x4<<<(n4 + 255) / 256, 256>>>((const float4*)x, (uint2*)xf, n4);
        n4 = EMBD * QKV_N / 4;
        tofp16x4<<<(n4 + 255) / 256, 256>>>((const float4*)W_qkv, (uint2*)wqf, n4);
        n4 = EMBD * EMBD / 4;
        tofp16x4<<<(n4 + 255) / 256, 256>>>((const float4*)W_out, (uint2*)wof, n4);
    }
    // 2) QKV projection (fp16, fp32 accumulate) -> fp16 qkv
    {
        dim3 grid(QKV_N / GBN, M / GBM);
        gemm_f16<2><<<grid, 128, GEMM_SMEM>>>(xf, wqf, b_qkv, nullptr, qkvf, M, QKV_N, EMBD);
    }
    // 3) Flash attention (fp16 MMA) -> fp16 attn output
    {
        dim3 grid(SEQ / 128, BATCH * NHEAD);
        flash_attn_mma<<<grid, 256, FLASH_SMEM>>>(qkvf, af);
    }
    // 4) Output projection (fp16, fp32 accumulate) -> fp32 result
    {
        dim3 grid(EMBD / GBN, M / GBM);
        gemm_f16<0><<<grid, 128, GEMM_SMEM>>>(af, wof, b_out, out, nullptr, M, EMBD, EMBD);
    }
}

// round 12
// speedup vs baseline: 1.0580x; 1.0580x over previous
#include <cuda_runtime.h>
#include <cuda_bf16.h>
#include <cuda_fp16.h>

// Problem constants
#define BATCH 4
#define SEQ   2048
#define EMBD  1024
#define NHEAD 16
#define HDIM  64
#define QKV_N (3*EMBD)

// ---------------------------------------------------------------------------
// Scratch (device globals: allocation-free, graph-capture safe)
// ---------------------------------------------------------------------------
__device__ __align__(256) __half g_xf[(size_t)BATCH * SEQ * EMBD];
__device__ __align__(256) __half g_wqf[(size_t)EMBD * QKV_N];
__device__ __align__(256) __half g_wof[(size_t)EMBD * EMBD];
__device__ __align__(256) __half g_qkvf[(size_t)BATCH * SEQ * QKV_N];
__device__ __align__(256) __half g_af[(size_t)BATCH * SEQ * EMBD];

// ---------------------------------------------------------------------------
// Common PTX helpers
// ---------------------------------------------------------------------------
__device__ __forceinline__ unsigned sptr(const void* p) {
    return (unsigned)__cvta_generic_to_shared(p);
}
__device__ __forceinline__ void cpa16(unsigned s, const void* g) {
    asm volatile("cp.async.cg.shared.global [%0], [%1], 16;\n" :: "r"(s), "l"(g));
}
__device__ __forceinline__ void ldsm4(unsigned* r, unsigned a) {
    asm volatile("ldmatrix.sync.aligned.m8n8.x4.shared.b16 {%0,%1,%2,%3},[%4];"
                 : "=r"(r[0]), "=r"(r[1]), "=r"(r[2]), "=r"(r[3]) : "r"(a));
}
__device__ __forceinline__ void ldsm4t(unsigned* r, unsigned a) {
    asm volatile("ldmatrix.sync.aligned.m8n8.x4.trans.shared.b16 {%0,%1,%2,%3},[%4];"
                 : "=r"(r[0]), "=r"(r[1]), "=r"(r[2]), "=r"(r[3]) : "r"(a));
}
__device__ __forceinline__ void mma16816h(float* d, const unsigned* a, const unsigned* b) {
    asm volatile(
        "mma.sync.aligned.m16n8k16.row.col.f32.f16.f16.f32 "
        "{%0,%1,%2,%3},{%4,%5,%6,%7},{%8,%9},{%0,%1,%2,%3};"
        : "+f"(d[0]), "+f"(d[1]), "+f"(d[2]), "+f"(d[3])
        : "r"(a[0]), "r"(a[1]), "r"(a[2]), "r"(a[3]), "r"(b[0]), "r"(b[1]));
}
__device__ __forceinline__ unsigned packh2(float a, float b) {
    __half2 hv = __floats2half2_rn(a, b);
    return *(unsigned*)&hv;
}

// ---------------------------------------------------------------------------
// fp32 -> fp16 convert, vectorized x4
// ---------------------------------------------------------------------------
__global__ __launch_bounds__(256) void tofp16x4(
    const float4* __restrict__ in, uint2* __restrict__ out, int n4)
{
    int i = blockIdx.x * blockDim.x + threadIdx.x;
    if (i >= n4) return;
    float4 v = in[i];
    uint2 o;
    o.x = packh2(v.x, v.y);
    o.y = packh2(v.z, v.w);
    out[i] = o;
}

// ---------------------------------------------------------------------------
// Tensor-core fp16 GEMM: C[M,N] = A[M,K] @ B[K,N] + bias, fp32 accumulate.
// 128 threads, 4 warps, warp tile 64x64, CTA tile 128x128, GBK=32.
// 3-stage cp.async ring, ONE __syncthreads per iteration, 2 CTAs/SM.
// OMODE 0: write fp32 C.   OMODE 2: write fp16 C.
// ---------------------------------------------------------------------------
#define GBM 128
#define GBN 128
#define GBK 32
#define APITCH 40                  // 32 + 8 pad (halves)
#define BPITCH 136                 // 128 + 8 pad (halves)
#define ASZ (128*APITCH)           // 5120 halves
#define BSZ (32*BPITCH)            // 4352 halves
#define NSTG 3
#define GEMM_SMEM (NSTG*(ASZ + BSZ)*2)   // 56832 bytes

template<int OMODE>
__global__ __launch_bounds__(128, 2) void gemm_f16(
    const __half* __restrict__ A, const __half* __restrict__ B,
    const float* __restrict__ bias,
    float* __restrict__ C, __half* __restrict__ Cf,
    int M, int N, int K)
{
    extern __shared__ char smem[];
    __half* sA = (__half*)smem;                 // [NSTG][ASZ]
    __half* sB = sA + NSTG * ASZ;               // [NSTG][BSZ]

    const int tid  = threadIdx.x;
    const int lane = tid & 31;
    const int warp = tid >> 5;
    const int bm   = blockIdx.y * GBM;
    const int bn   = blockIdx.x * GBN;
    const int wm   = (warp & 1) * 64;
    const int wn   = (warp >> 1) * 64;

    float acc[4][8][4];
#pragma unroll
    for (int mi = 0; mi < 4; mi++)
#pragma unroll
        for (int n = 0; n < 8; n++)
#pragma unroll
            for (int e = 0; e < 4; e++) acc[mi][n][e] = 0.f;

    const int NIT = K / GBK;
    // always commits (possibly empty group) to keep wait counts invariant
    auto prefetch = [&](int stg, int it) {
        if (it < NIT) {
            const int k0 = it * GBK;
            const __half* a = A + (size_t)bm * K + k0;
#pragma unroll
            for (int i = 0; i < 4; i++) {
                int idx = tid + i * 128;
                int r = idx >> 2, c = (idx & 3) * 8;
                cpa16(sptr(&sA[stg * ASZ + r * APITCH + c]), a + (size_t)r * K + c);
            }
            const __half* b = B + (size_t)k0 * N + bn;
#pragma unroll
            for (int i = 0; i < 4; i++) {
                int idx = tid + i * 128;
                int r = idx >> 4, c = (idx & 15) * 8;
                cpa16(sptr(&sB[stg * BSZ + r * BPITCH + c]), b + (size_t)r * N + c);
            }
        }
        asm volatile("cp.async.commit_group;");
    };

    prefetch(0, 0);
    prefetch(1, 1);
    int st = 0;
    for (int it = 0; it < NIT; it++) {
        asm volatile("cp.async.wait_group 1;");
        __syncthreads();
        int nxt = st + 2; if (nxt >= NSTG) nxt -= NSTG;
        prefetch(nxt, it + 2);

#pragma unroll
        for (int kk = 0; kk < GBK; kk += 16) {
            unsigned af[4][4], bf[4][4];
#pragma unroll
            for (int mi = 0; mi < 4; mi++) {
                int row = wm + mi * 16 + (lane & 15);
                int col = kk + (lane >> 4) * 8;
                ldsm4(af[mi], sptr(&sA[st * ASZ + row * APITCH + col]));
            }
#pragma unroll
            for (int nj = 0; nj < 4; nj++) {
                int row = kk + (lane & 15);
                int col = wn + nj * 16 + (lane >> 4) * 8;
                ldsm4t(bf[nj], sptr(&sB[st * BSZ + row * BPITCH + col]));
            }
#pragma unroll
            for (int mi = 0; mi < 4; mi++)
#pragma unroll
                for (int nj = 0; nj < 4; nj++)
#pragma unroll
                    for (int sub = 0; sub < 2; sub++)
                        mma16816h(acc[mi][nj * 2 + sub], af[mi], &bf[nj][sub * 2]);
        }
        if (++st >= NSTG) st = 0;
    }

#pragma unroll
    for (int mi = 0; mi < 4; mi++) {
        int r0 = bm + wm + mi * 16 + (lane >> 2);
#pragma unroll
        for (int n = 0; n < 8; n++) {
            int c0 = bn + wn + n * 8 + (lane & 3) * 2;
            float2 bv = *(const float2*)(bias + c0);
            float v00 = acc[mi][n][0] + bv.x, v01 = acc[mi][n][1] + bv.y;
            float v10 = acc[mi][n][2] + bv.x, v11 = acc[mi][n][3] + bv.y;
            if (OMODE == 0) {
                *(float2*)(C + (size_t)r0 * N + c0) = make_float2(v00, v01);
                *(float2*)(C + (size_t)(r0 + 8) * N + c0) = make_float2(v10, v11);
            } else {
                *(unsigned*)(Cf + (size_t)r0 * N + c0) = packh2(v00, v01);
                *(unsigned*)(Cf + (size_t)(r0 + 8) * N + c0) = packh2(v10, v11);
            }
        }
    }
}

// ---------------------------------------------------------------------------
// Tensor-core causal flash attention, single fp16 MMA path, log2-domain
// softmax, 3-stage cp.async ring with one __syncthreads per tile.
// ---------------------------------------------------------------------------
#define KPH 72
#define TSZH (64*KPH)              // halves per tensor tile
#define STGH (2*TSZH)              // K, V per stage
#define FLASH_SMEM (NSTG*STGH*2)   // 55296 bytes
#define SCALE_L2E 0.1803368801f    // 0.125 * log2(e)

__global__ __launch_bounds__(256, 2) void flash_attn_mma(
    const __half* __restrict__ qkv, __half* __restrict__ outf)
{
    extern __shared__ char smraw[];
    __half* sm = (__half*)smraw;

    const int tid  = threadIdx.x;
    const int lane = tid & 31;
    const int warp = tid >> 5;
    const int bh   = blockIdx.y;
    const int b    = bh >> 4;
    const int h    = bh & (NHEAD - 1);
    const int qb   = (gridDim.x - 1) - blockIdx.x;  // heavy tiles first
    const int q0   = qb * 128;
    const int wm   = warp * 16;
    const int r    = lane >> 2;
    const int cp   = (lane & 3) * 2;
    const int qrow = q0 + wm + r;

    // ---- Q fragments straight from global (packed half2 = one u32) ----
    unsigned qf[4][4];
    {
        const size_t base  = ((size_t)(b * SEQ) + qrow) * QKV_N + h * HDIM;
        const size_t base8 = base + (size_t)8 * QKV_N;
#pragma unroll
        for (int kk = 0; kk < 4; kk++) {
            int c0 = kk * 16 + cp;
            qf[kk][0] = *(const unsigned*)(qkv + base  + c0);
            qf[kk][1] = *(const unsigned*)(qkv + base8 + c0);
            qf[kk][2] = *(const unsigned*)(qkv + base  + c0 + 8);
            qf[kk][3] = *(const unsigned*)(qkv + base8 + c0 + 8);
        }
    }

    float m0 = -1e30f, m1 = -1e30f, l0 = 0.f, l1 = 0.f;
    float o[8][4];
#pragma unroll
    for (int nf = 0; nf < 8; nf++)
#pragma unroll
        for (int e = 0; e < 4; e++) o[nf][e] = 0.f;

    const size_t koff = (size_t)EMBD + h * HDIM;
    const size_t voff = (size_t)(2 * EMBD) + h * HDIM;

    const int ntiles = 2 * qb + 2;
    auto prefetch = [&](int stg, int t) {
        if (t < ntiles) {
            const int k0 = t * 64;
#pragma unroll
            for (int i = 0; i < 4; i++) {
                int id = tid + i * 256;           // 0..1023
                int tt = id >> 9;                 // 0:K 1:V
                int rr = (id >> 3) & 63;
                int cc = (id & 7) * 8;
                const __half* src = qkv + ((size_t)(b * SEQ) + k0 + rr) * QKV_N
                                  + (tt ? voff : koff) + cc;
                cpa16(sptr(&sm[stg * STGH + tt * TSZH + rr * KPH + cc]), src);
            }
        }
        asm volatile("cp.async.commit_group;");
    };

    prefetch(0, 0);
    prefetch(1, 1);
    int st = 0;
    for (int t = 0; t < ntiles; t++) {
        const int k0 = t * 64;
        asm volatile("cp.async.wait_group 1;");
        __syncthreads();
        int nxt = st + 2; if (nxt >= NSTG) nxt -= NSTG;
        prefetch(nxt, t + 2);

        if (k0 <= q0 + wm + 15) {   // causal warp-level skip
            const __half* Kf = sm + st * STGH;
            const __half* Vf = sm + st * STGH + TSZH;

            // ---- S = Q K^T ----
            float s[8][4];
#pragma unroll
            for (int nf = 0; nf < 8; nf++)
#pragma unroll
                for (int e = 0; e < 4; e++) s[nf][e] = 0.f;

#pragma unroll
            for (int kk = 0; kk < 4; kk++) {
#pragma unroll
                for (int g = 0; g < 4; g++) {
                    unsigned kf4[4];
                    int off = (16 * g + (lane & 15)) * KPH + kk * 16 + (lane >> 4) * 8;
                    ldsm4(kf4, sptr(Kf + off));
                    unsigned b0[2] = {kf4[0], kf4[2]}, b1[2] = {kf4[1], kf4[3]};
                    mma16816h(s[2*g],     qf[kk], b0);
                    mma16816h(s[2*g + 1], qf[kk], b1);
                }
            }

            // ---- masking + online softmax (log2 domain) ----
            const bool need_mask = (k0 + 63) > (q0 + wm);
            float mx0 = -1e30f, mx1 = -1e30f;
#pragma unroll
            for (int nf = 0; nf < 8; nf++) {
#pragma unroll
                for (int e = 0; e < 4; e++) s[nf][e] *= SCALE_L2E;
                if (need_mask) {
                    int c0 = k0 + nf * 8 + cp;
                    if (c0     > qrow)     s[nf][0] = -1e30f;
                    if (c0 + 1 > qrow)     s[nf][1] = -1e30f;
                    if (c0     > qrow + 8) s[nf][2] = -1e30f;
                    if (c0 + 1 > qrow + 8) s[nf][3] = -1e30f;
                }
                mx0 = fmaxf(mx0, fmaxf(s[nf][0], s[nf][1]));
                mx1 = fmaxf(mx1, fmaxf(s[nf][2], s[nf][3]));
            }
            mx0 = fmaxf(mx0, __shfl_xor_sync(0xffffffffu, mx0, 1));
            mx0 = fmaxf(mx0, __shfl_xor_sync(0xffffffffu, mx0, 2));
            mx1 = fmaxf(mx1, __shfl_xor_sync(0xffffffffu, mx1, 1));
            mx1 = fmaxf(mx1, __shfl_xor_sync(0xffffffffu, mx1, 2));

            const float nm0 = fmaxf(m0, mx0), nm1 = fmaxf(m1, mx1);
            const float cr0 = exp2f(m0 - nm0), cr1 = exp2f(m1 - nm1);
            m0 = nm0; m1 = nm1;
            l0 *= cr0; l1 *= cr1;
#pragma unroll
            for (int nf = 0; nf < 8; nf++) {
                o[nf][0] *= cr0; o[nf][1] *= cr0;
                o[nf][2] *= cr1; o[nf][3] *= cr1;
            }

            unsigned pf[8][2];
#pragma unroll
            for (int nf = 0; nf < 8; nf++) {
                float p0 = exp2f(s[nf][0] - m0);
                float p1 = exp2f(s[nf][1] - m0);
                float p2 = exp2f(s[nf][2] - m1);
                float p3 = exp2f(s[nf][3] - m1);
                l0 += p0 + p1;
                l1 += p2 + p3;
                pf[nf][0] = packh2(p0, p1);
                pf[nf][1] = packh2(p2, p3);
            }

            // ---- O += P V ----
#pragma unroll
            for (int kp = 0; kp < 4; kp++) {
                unsigned pa[4] = {pf[2*kp][0], pf[2*kp][1], pf[2*kp+1][0], pf[2*kp+1][1]};
#pragma unroll
                for (int dg = 0; dg < 4; dg++) {
                    unsigned vf4[4];
                    int off = (kp * 16 + (lane & 15)) * KPH + dg * 16 + (lane >> 4) * 8;
                    ldsm4t(vf4, sptr(Vf + off));
                    mma16816h(o[2*dg],     pa, &vf4[0]);
                    mma16816h(o[2*dg + 1], pa, &vf4[2]);
                }
            }
        }
        if (++st >= NSTG) st = 0;
    }

    // ---- finalize: quad-reduce l, normalize, store fp16 ----
    l0 += __shfl_xor_sync(0xffffffffu, l0, 1);
    l0 += __shfl_xor_sync(0xffffffffu, l0, 2);
    l1 += __shfl_xor_sync(0xffffffffu, l1, 1);
    l1 += __shfl_xor_sync(0xffffffffu, l1, 2);
    const float inv0 = 1.f / l0, inv1 = 1.f / l1;

    const size_t obase  = ((size_t)(b * SEQ) + qrow) * EMBD + h * HDIM;
    const size_t obase8 = obase + (size_t)8 * EMBD;
#pragma unroll
    for (int nf = 0; nf < 8; nf++) {
        int c0 = nf * 8 + cp;
        *(unsigned*)(outf + obase  + c0) = packh2(o[nf][0] * inv0, o[nf][1] * inv0);
        *(unsigned*)(outf + obase8 + c0) = packh2(o[nf][2] * inv1, o[nf][3] * inv1);
    }
}

// ---------------------------------------------------------------------------
// Launch
// ---------------------------------------------------------------------------
extern "C" void kernel_launch(void* const* d_in, const int* in_sizes, int n_in,
                              void* d_out, int out_size)
{
    const float* x     = (const float*)d_in[0];
    const float* W_qkv = (const float*)d_in[1];
    const float* b_qkv = (const float*)d_in[2];
    const float* W_out = (const float*)d_in[3];
    const float* b_out = (const float*)d_in[4];
    float* out = (float*)d_out;

    __half *xf, *wqf, *wof, *qkvf, *af;
    cudaGetSymbolAddress((void**)&xf,   g_xf);
    cudaGetSymbolAddress((void**)&wqf,  g_wqf);
    cudaGetSymbolAddress((void**)&wof,  g_wof);
    cudaGetSymbolAddress((void**)&qkvf, g_qkvf);
    cudaGetSymbolAddress((void**)&af,   g_af);

    const int M = BATCH * SEQ;                       // 8192

    cudaFuncSetAttribute(gemm_f16<0>, cudaFuncAttributeMaxDynamicSharedMemorySize, GEMM_SMEM);
    cudaFuncSetAttribute(gemm_f16<2>, cudaFuncAttributeMaxDynamicSharedMemorySize, GEMM_SMEM);
    cudaFuncSetAttribute(flash_attn_mma, cudaFuncAttributeMaxDynamicSharedMemorySize, FLASH_SMEM);

    // 1) convert inputs to fp16
    {
        int n4 = M * EMBD / 4;
        tofp16x4<<<(n4 + 255) / 256, 256>>>((const float4*)x, (uint2*)xf, n4);
        n4 = EMBD * QKV_N / 4;
        tofp16x4<<<(n4 + 255) / 256, 256>>>((const float4*)W_qkv, (uint2*)wqf, n4);
        n4 = EMBD * EMBD / 4;
        tofp16x4<<<(n4 + 255) / 256, 256>>>((const float4*)W_out, (uint2*)wof, n4);
    }
    // 2) QKV projection (fp16, fp32 accumulate) -> fp16 qkv
    {
        dim3 grid(QKV_N / GBN, M / GBM);
        gemm_f16<2><<<grid, 128, GEMM_SMEM>>>(xf, wqf, b_qkv, nullptr, qkvf, M, QKV_N, EMBD);
    }
    // 3) Flash attention (fp16 MMA) -> fp16 attn output
    {
        dim3 grid(SEQ / 128, BATCH * NHEAD);
        flash_attn_mma<<<grid, 256, FLASH_SMEM>>>(qkvf, af);
    }
    // 4) Output projection (fp16, fp32 accumulate) -> fp32 result
    {
        dim3 grid(EMBD / GBN, M / GBM);
        gemm_f16<0><<<grid, 128, GEMM_SMEM>>>(af, wof, b_out, out, nullptr, M, EMBD, EMBD);
    }
}

// round 15
// speedup vs baseline: 1.0684x; 1.0098x over previous
#include <cuda_runtime.h>
#include <cuda_bf16.h>
#include <cuda_fp16.h>

// Problem constants
#define BATCH 4
#define SEQ   2048
#define EMBD  1024
#define NHEAD 16
#define HDIM  64
#define QKV_N (3*EMBD)

// ---------------------------------------------------------------------------
// Scratch (device globals: allocation-free, graph-capture safe)
// ---------------------------------------------------------------------------
__device__ __align__(256) __half g_xf[(size_t)BATCH * SEQ * EMBD];
__device__ __align__(256) __half g_wqf[(size_t)EMBD * QKV_N];
__device__ __align__(256) __half g_wof[(size_t)EMBD * EMBD];
__device__ __align__(256) __half g_qkvf[(size_t)BATCH * SEQ * QKV_N];
__device__ __align__(256) __half g_af[(size_t)BATCH * SEQ * EMBD];

// ---------------------------------------------------------------------------
// Common PTX helpers
// ---------------------------------------------------------------------------
__device__ __forceinline__ unsigned sptr(const void* p) {
    return (unsigned)__cvta_generic_to_shared(p);
}
__device__ __forceinline__ void cpa16(unsigned s, const void* g) {
    asm volatile("cp.async.cg.shared.global [%0], [%1], 16;\n" :: "r"(s), "l"(g));
}
__device__ __forceinline__ void ldsm4(unsigned* r, unsigned a) {
    asm volatile("ldmatrix.sync.aligned.m8n8.x4.shared.b16 {%0,%1,%2,%3},[%4];"
                 : "=r"(r[0]), "=r"(r[1]), "=r"(r[2]), "=r"(r[3]) : "r"(a));
}
__device__ __forceinline__ void ldsm4t(unsigned* r, unsigned a) {
    asm volatile("ldmatrix.sync.aligned.m8n8.x4.trans.shared.b16 {%0,%1,%2,%3},[%4];"
                 : "=r"(r[0]), "=r"(r[1]), "=r"(r[2]), "=r"(r[3]) : "r"(a));
}
__device__ __forceinline__ void mma16816h(float* d, const unsigned* a, const unsigned* b) {
    asm volatile(
        "mma.sync.aligned.m16n8k16.row.col.f32.f16.f16.f32 "
        "{%0,%1,%2,%3},{%4,%5,%6,%7},{%8,%9},{%0,%1,%2,%3};"
        : "+f"(d[0]), "+f"(d[1]), "+f"(d[2]), "+f"(d[3])
        : "r"(a[0]), "r"(a[1]), "r"(a[2]), "r"(a[3]), "r"(b[0]), "r"(b[1]));
}
__device__ __forceinline__ unsigned packh2(float a, float b) {
    __half2 hv = __floats2half2_rn(a, b);
    return *(unsigned*)&hv;
}

// ---------------------------------------------------------------------------
// fp32 -> fp16 convert, vectorized x4
// ---------------------------------------------------------------------------
__global__ __launch_bounds__(256) void tofp16x4(
    const float4* __restrict__ in, uint2* __restrict__ out, int n4)
{
    int i = blockIdx.x * blockDim.x + threadIdx.x;
    if (i >= n4) return;
    float4 v = in[i];
    uint2 o;
    o.x = packh2(v.x, v.y);
    o.y = packh2(v.z, v.w);
    out[i] = o;
}

// ---------------------------------------------------------------------------
// Tensor-core fp16 GEMM (unchanged from R12 best): CTA 128x128, GBK=32,
// 3-stage ring, one __syncthreads per iteration, 2 CTAs/SM.
// ---------------------------------------------------------------------------
#define GBM 128
#define GBN 128
#define GBK 32
#define APITCH 40
#define BPITCH 136
#define ASZ (128*APITCH)
#define BSZ (32*BPITCH)
#define NSTG 3
#define GEMM_SMEM (NSTG*(ASZ + BSZ)*2)

template<int OMODE>
__global__ __launch_bounds__(128, 2) void gemm_f16(
    const __half* __restrict__ A, const __half* __restrict__ B,
    const float* __restrict__ bias,
    float* __restrict__ C, __half* __restrict__ Cf,
    int M, int N, int K)
{
    extern __shared__ char smem[];
    __half* sA = (__half*)smem;
    __half* sB = sA + NSTG * ASZ;

    const int tid  = threadIdx.x;
    const int lane = tid & 31;
    const int warp = tid >> 5;
    const int bm   = blockIdx.y * GBM;
    const int bn   = blockIdx.x * GBN;
    const int wm   = (warp & 1) * 64;
    const int wn   = (warp >> 1) * 64;

    float acc[4][8][4];
#pragma unroll
    for (int mi = 0; mi < 4; mi++)
#pragma unroll
        for (int n = 0; n < 8; n++)
#pragma unroll
            for (int e = 0; e < 4; e++) acc[mi][n][e] = 0.f;

    const int NIT = K / GBK;
    auto prefetch = [&](int stg, int it) {
        if (it < NIT) {
            const int k0 = it * GBK;
            const __half* a = A + (size_t)bm * K + k0;
#pragma unroll
            for (int i = 0; i < 4; i++) {
                int idx = tid + i * 128;
                int r = idx >> 2, c = (idx & 3) * 8;
                cpa16(sptr(&sA[stg * ASZ + r * APITCH + c]), a + (size_t)r * K + c);
            }
            const __half* b = B + (size_t)k0 * N + bn;
#pragma unroll
            for (int i = 0; i < 4; i++) {
                int idx = tid + i * 128;
                int r = idx >> 4, c = (idx & 15) * 8;
                cpa16(sptr(&sB[stg * BSZ + r * BPITCH + c]), b + (size_t)r * N + c);
            }
        }
        asm volatile("cp.async.commit_group;");
    };

    prefetch(0, 0);
    prefetch(1, 1);
    int st = 0;
    for (int it = 0; it < NIT; it++) {
        asm volatile("cp.async.wait_group 1;");
        __syncthreads();
        int nxt = st + 2; if (nxt >= NSTG) nxt -= NSTG;
        prefetch(nxt, it + 2);

#pragma unroll
        for (int kk = 0; kk < GBK; kk += 16) {
            unsigned af[4][4], bf[4][4];
#pragma unroll
            for (int mi = 0; mi < 4; mi++) {
                int row = wm + mi * 16 + (lane & 15);
                int col = kk + (lane >> 4) * 8;
                ldsm4(af[mi], sptr(&sA[st * ASZ + row * APITCH + col]));
            }
#pragma unroll
            for (int nj = 0; nj < 4; nj++) {
                int row = kk + (lane & 15);
                int col = wn + nj * 16 + (lane >> 4) * 8;
                ldsm4t(bf[nj], sptr(&sB[st * BSZ + row * BPITCH + col]));
            }
#pragma unroll
            for (int mi = 0; mi < 4; mi++)
#pragma unroll
                for (int nj = 0; nj < 4; nj++)
#pragma unroll
                    for (int sub = 0; sub < 2; sub++)
                        mma16816h(acc[mi][nj * 2 + sub], af[mi], &bf[nj][sub * 2]);
        }
        if (++st >= NSTG) st = 0;
    }

#pragma unroll
    for (int mi = 0; mi < 4; mi++) {
        int r0 = bm + wm + mi * 16 + (lane >> 2);
#pragma unroll
        for (int n = 0; n < 8; n++) {
            int c0 = bn + wn + n * 8 + (lane & 3) * 2;
            float2 bv = *(const float2*)(bias + c0);
            float v00 = acc[mi][n][0] + bv.x, v01 = acc[mi][n][1] + bv.y;
            float v10 = acc[mi][n][2] + bv.x, v11 = acc[mi][n][3] + bv.y;
            if (OMODE == 0) {
                *(float2*)(C + (size_t)r0 * N + c0) = make_float2(v00, v01);
                *(float2*)(C + (size_t)(r0 + 8) * N + c0) = make_float2(v10, v11);
            } else {
                *(unsigned*)(Cf + (size_t)r0 * N + c0) = packh2(v00, v01);
                *(unsigned*)(Cf + (size_t)(r0 + 8) * N + c0) = packh2(v10, v11);
            }
        }
    }
}

// ---------------------------------------------------------------------------
// Flash attention: 128 threads, 4 warps x 32 q rows (MMA:LDSM = 4),
// fp16 MMA, log2-domain softmax, 3-stage K/V ring, 2 CTAs/SM.
// ---------------------------------------------------------------------------
#define KPH 72
#define TSZH (64*KPH)
#define STGH (2*TSZH)
#define FLASH_SMEM (NSTG*STGH*2)   // 55296 bytes
#define SCALE_L2E 0.1803368801f    // 0.125 * log2(e)

__global__ __launch_bounds__(128, 2) void flash_attn_mma(
    const __half* __restrict__ qkv, __half* __restrict__ outf)
{
    extern __shared__ char smraw[];
    __half* sm = (__half*)smraw;

    const int tid  = threadIdx.x;
    const int lane = tid & 31;
    const int warp = tid >> 5;                      // 0..3
    const int bh   = blockIdx.y;
    const int b    = bh >> 4;
    const int h    = bh & (NHEAD - 1);
    const int qb   = (gridDim.x - 1) - blockIdx.x;  // heavy tiles first
    const int q0   = qb * 128;
    const int wm   = warp * 32;                     // 32 q rows per warp
    const int r    = lane >> 2;
    const int cp   = (lane & 3) * 2;

    // ---- Q fragments (2 row-groups of 16) straight from global ----
    unsigned qf[4][2][4];
#pragma unroll
    for (int mi = 0; mi < 2; mi++) {
        const size_t base  = ((size_t)(b * SEQ) + q0 + wm + mi * 16 + r) * QKV_N + h * HDIM;
        const size_t base8 = base + (size_t)8 * QKV_N;
#pragma unroll
        for (int kk = 0; kk < 4; kk++) {
            int c0 = kk * 16 + cp;
            qf[kk][mi][0] = *(const unsigned*)(qkv + base  + c0);
            qf[kk][mi][1] = *(const unsigned*)(qkv + base8 + c0);
            qf[kk][mi][2] = *(const unsigned*)(qkv + base  + c0 + 8);
            qf[kk][mi][3] = *(const unsigned*)(qkv + base8 + c0 + 8);
        }
    }

    float m[4] = {-1e30f, -1e30f, -1e30f, -1e30f};  // [mi*2 + (0:r,1:r+8)]
    float l[4] = {0.f, 0.f, 0.f, 0.f};
    float o[2][8][4];
#pragma unroll
    for (int mi = 0; mi < 2; mi++)
#pragma unroll
        for (int nf = 0; nf < 8; nf++)
#pragma unroll
            for (int e = 0; e < 4; e++) o[mi][nf][e] = 0.f;

    const size_t koff = (size_t)EMBD + h * HDIM;
    const size_t voff = (size_t)(2 * EMBD) + h * HDIM;

    const int ntiles = 2 * qb + 2;
    auto prefetch = [&](int stg, int t) {
        if (t < ntiles) {
            const int k0 = t * 64;
#pragma unroll
            for (int i = 0; i < 8; i++) {
                int id = tid + i * 128;           // 0..1023
                int tt = id >> 9;                 // 0:K 1:V
                int rr = (id >> 3) & 63;
                int cc = (id & 7) * 8;
                const __half* src = qkv + ((size_t)(b * SEQ) + k0 + rr) * QKV_N
                                  + (tt ? voff : koff) + cc;
                cpa16(sptr(&sm[stg * STGH + tt * TSZH + rr * KPH + cc]), src);
            }
        }
        asm volatile("cp.async.commit_group;");
    };

    prefetch(0, 0);
    prefetch(1, 1);
    int st = 0;
    for (int t = 0; t < ntiles; t++) {
        const int k0 = t * 64;
        asm volatile("cp.async.wait_group 1;");
        __syncthreads();
        int nxt = st + 2; if (nxt >= NSTG) nxt -= NSTG;
        prefetch(nxt, t + 2);

        if (k0 <= q0 + wm + 31) {   // causal warp-level skip
            const __half* Kf = sm + st * STGH;
            const __half* Vf = sm + st * STGH + TSZH;

            // ---- S = Q K^T ----
            float s[2][8][4];
#pragma unroll
            for (int mi = 0; mi < 2; mi++)
#pragma unroll
                for (int nf = 0; nf < 8; nf++)
#pragma unroll
                    for (int e = 0; e < 4; e++) s[mi][nf][e] = 0.f;

#pragma unroll
            for (int kk = 0; kk < 4; kk++) {
#pragma unroll
                for (int g = 0; g < 4; g++) {
                    unsigned kf4[4];
                    int off = (16 * g + (lane & 15)) * KPH + kk * 16 + (lane >> 4) * 8;
                    ldsm4(kf4, sptr(Kf + off));
                    unsigned b0[2] = {kf4[0], kf4[2]}, b1[2] = {kf4[1], kf4[3]};
#pragma unroll
                    for (int mi = 0; mi < 2; mi++) {
                        mma16816h(s[mi][2*g],     qf[kk][mi], b0);
                        mma16816h(s[mi][2*g + 1], qf[kk][mi], b1);
                    }
                }
            }

            // ---- masking + online softmax (log2 domain), per row-group ----
            unsigned pf[2][8][2];
#pragma unroll
            for (int mi = 0; mi < 2; mi++) {
                const int qrow = q0 + wm + mi * 16 + r;
                const bool need_mask = (k0 + 63) > (q0 + wm + mi * 16);
                float mx0 = -1e30f, mx1 = -1e30f;
#pragma unroll
                for (int nf = 0; nf < 8; nf++) {
#pragma unroll
                    for (int e = 0; e < 4; e++) s[mi][nf][e] *= SCALE_L2E;
                    if (need_mask) {
                        int c0 = k0 + nf * 8 + cp;
                        if (c0     > qrow)     s[mi][nf][0] = -1e30f;
                        if (c0 + 1 > qrow)     s[mi][nf][1] = -1e30f;
                        if (c0     > qrow + 8) s[mi][nf][2] = -1e30f;
                        if (c0 + 1 > qrow + 8) s[mi][nf][3] = -1e30f;
                    }
                    mx0 = fmaxf(mx0, fmaxf(s[mi][nf][0], s[mi][nf][1]));
                    mx1 = fmaxf(mx1, fmaxf(s[mi][nf][2], s[mi][nf][3]));
                }
                mx0 = fmaxf(mx0, __shfl_xor_sync(0xffffffffu, mx0, 1));
                mx0 = fmaxf(mx0, __shfl_xor_sync(0xffffffffu, mx0, 2));
                mx1 = fmaxf(mx1, __shfl_xor_sync(0xffffffffu, mx1, 1));
                mx1 = fmaxf(mx1, __shfl_xor_sync(0xffffffffu, mx1, 2));

                const float nm0 = fmaxf(m[2*mi], mx0), nm1 = fmaxf(m[2*mi+1], mx1);
                const float cr0 = exp2f(m[2*mi] - nm0), cr1 = exp2f(m[2*mi+1] - nm1);
                m[2*mi] = nm0; m[2*mi+1] = nm1;
                l[2*mi] *= cr0; l[2*mi+1] *= cr1;
#pragma unroll
                for (int nf = 0; nf < 8; nf++) {
                    o[mi][nf][0] *= cr0; o[mi][nf][1] *= cr0;
                    o[mi][nf][2] *= cr1; o[mi][nf][3] *= cr1;
                }
#pragma unroll
                for (int nf = 0; nf < 8; nf++) {
                    float p0 = exp2f(s[mi][nf][0] - nm0);
                    float p1 = exp2f(s[mi][nf][1] - nm0);
                    float p2 = exp2f(s[mi][nf][2] - nm1);
                    float p3 = exp2f(s[mi][nf][3] - nm1);
                    l[2*mi]   += p0 + p1;
                    l[2*mi+1] += p2 + p3;
                    pf[mi][nf][0] = packh2(p0, p1);
                    pf[mi][nf][1] = packh2(p2, p3);
                }
            }

            // ---- O += P V ----
#pragma unroll
            for (int kp = 0; kp < 4; kp++) {
                unsigned pa0[4] = {pf[0][2*kp][0], pf[0][2*kp][1], pf[0][2*kp+1][0], pf[0][2*kp+1][1]};
                unsigned pa1[4] = {pf[1][2*kp][0], pf[1][2*kp][1], pf[1][2*kp+1][0], pf[1][2*kp+1][1]};
#pragma unroll
                for (int dg = 0; dg < 4; dg++) {
                    unsigned vf4[4];
                    int off = (kp * 16 + (lane & 15)) * KPH + dg * 16 + (lane >> 4) * 8;
                    ldsm4t(vf4, sptr(Vf + off));
                    mma16816h(o[0][2*dg],     pa0, &vf4[0]);
                    mma16816h(o[0][2*dg + 1], pa0, &vf4[2]);
                    mma16816h(o[1][2*dg],     pa1, &vf4[0]);
                    mma16816h(o[1][2*dg + 1], pa1, &vf4[2]);
                }
            }
        }
        if (++st >= NSTG) st = 0;
    }

    // ---- finalize: quad-reduce l, normalize, store fp16 ----
#pragma unroll
    for (int i = 0; i < 4; i++) {
        l[i] += __shfl_xor_sync(0xffffffffu, l[i], 1);
        l[i] += __shfl_xor_sync(0xffffffffu, l[i], 2);
    }
#pragma unroll
    for (int mi = 0; mi < 2; mi++) {
        const float inv0 = 1.f / l[2*mi], inv1 = 1.f / l[2*mi+1];
        const size_t obase  = ((size_t)(b * SEQ) + q0 + wm + mi * 16 + r) * EMBD + h * HDIM;
        const size_t obase8 = obase + (size_t)8 * EMBD;
#pragma unroll
        for (int nf = 0; nf < 8; nf++) {
            int c0 = nf * 8 + cp;
            *(unsigned*)(outf + obase  + c0) = packh2(o[mi][nf][0] * inv0, o[mi][nf][1] * inv0);
            *(unsigned*)(outf + obase8 + c0) = packh2(o[mi][nf][2] * inv1, o[mi][nf][3] * inv1);
        }
    }
}

// ---------------------------------------------------------------------------
// Launch
// ---------------------------------------------------------------------------
extern "C" void kernel_launch(void* const* d_in, const int* in_sizes, int n_in,
                              void* d_out, int out_size)
{
    const float* x     = (const float*)d_in[0];
    const float* W_qkv = (const float*)d_in[1];
    const float* b_qkv = (const float*)d_in[2];
    const float* W_out = (const float*)d_in[3];
    const float* b_out = (const float*)d_in[4];
    float* out = (float*)d_out;

    __half *xf, *wqf, *wof, *qkvf, *af;
    cudaGetSymbolAddress((void**)&xf,   g_xf);
    cudaGetSymbolAddress((void**)&wqf,  g_wqf);
    cudaGetSymbolAddress((void**)&wof,  g_wof);
    cudaGetSymbolAddress((void**)&qkvf, g_qkvf);
    cudaGetSymbolAddress((void**)&af,   g_af);

    const int M = BATCH * SEQ;                       // 8192

    cudaFuncSetAttribute(gemm_f16<0>, cudaFuncAttributeMaxDynamicSharedMemorySize, GEMM_SMEM);
    cudaFuncSetAttribute(gemm_f16<2>, cudaFuncAttributeMaxDynamicSharedMemorySize, GEMM_SMEM);
    cudaFuncSetAttribute(flash_attn_mma, cudaFuncAttributeMaxDynamicSharedMemorySize, FLASH_SMEM);

    // 1) convert inputs to fp16
    {
        int n4 = M * EMBD / 4;
        tofp16x4<<<(n4 + 255) / 256, 256>>>((const float4*)x, (uint2*)xf, n4);
        n4 = EMBD * QKV_N / 4;
        tofp16x4<<<(n4 + 255) / 256, 256>>>((const float4*)W_qkv, (uint2*)wqf, n4);
        n4 = EMBD * EMBD / 4;
        tofp16x4<<<(n4 + 255) / 256, 256>>>((const float4*)W_out, (uint2*)wof, n4);
    }
    // 2) QKV projection (fp16, fp32 accumulate) -> fp16 qkv
    {
        dim3 grid(QKV_N / GBN, M / GBM);
        gemm_f16<2><<<grid, 128, GEMM_SMEM>>>(xf, wqf, b_qkv, nullptr, qkvf, M, QKV_N, EMBD);
    }
    // 3) Flash attention (fp16 MMA, 4 warps x 32 rows) -> fp16 attn output
    {
        dim3 grid(SEQ / 128, BATCH * NHEAD);
        flash_attn_mma<<<grid, 128, FLASH_SMEM>>>(qkvf, af);
    }
    // 4) Output projection (fp16, fp32 accumulate) -> fp32 result
    {
        dim3 grid(EMBD / GBN, M / GBM);
        gemm_f16<0><<<grid, 128, GEMM_SMEM>>>(af, wof, b_out, out, nullptr, M, EMBD, EMBD);
    }
}

// round 17
// speedup vs baseline: 1.0789x; 1.0098x over previous
#include <cuda_runtime.h>
#include <cuda_bf16.h>
#include <cuda_fp16.h>

// Problem constants
#define BATCH 4
#define SEQ   2048
#define EMBD  1024
#define NHEAD 16
#define HDIM  64
#define QKV_N (3*EMBD)

// ---------------------------------------------------------------------------
// Scratch (device globals: allocation-free, graph-capture safe)
// ---------------------------------------------------------------------------
__device__ __align__(256) __half g_xf[(size_t)BATCH * SEQ * EMBD];
__device__ __align__(256) __half g_wqf[(size_t)EMBD * QKV_N];
__device__ __align__(256) __half g_wof[(size_t)EMBD * EMBD];
__device__ __align__(256) __half g_qkvf[(size_t)BATCH * SEQ * QKV_N];
__device__ __align__(256) __half g_af[(size_t)BATCH * SEQ * EMBD];

// ---------------------------------------------------------------------------
// Common PTX helpers
// ---------------------------------------------------------------------------
__device__ __forceinline__ unsigned sptr(const void* p) {
    return (unsigned)__cvta_generic_to_shared(p);
}
__device__ __forceinline__ void cpa16(unsigned s, const void* g) {
    asm volatile("cp.async.cg.shared.global [%0], [%1], 16;\n" :: "r"(s), "l"(g));
}
__device__ __forceinline__ void ldsm4(unsigned* r, unsigned a) {
    asm volatile("ldmatrix.sync.aligned.m8n8.x4.shared.b16 {%0,%1,%2,%3},[%4];"
                 : "=r"(r[0]), "=r"(r[1]), "=r"(r[2]), "=r"(r[3]) : "r"(a));
}
__device__ __forceinline__ void ldsm4t(unsigned* r, unsigned a) {
    asm volatile("ldmatrix.sync.aligned.m8n8.x4.trans.shared.b16 {%0,%1,%2,%3},[%4];"
                 : "=r"(r[0]), "=r"(r[1]), "=r"(r[2]), "=r"(r[3]) : "r"(a));
}
__device__ __forceinline__ void mma16816h(float* d, const unsigned* a, const unsigned* b) {
    asm volatile(
        "mma.sync.aligned.m16n8k16.row.col.f32.f16.f16.f32 "
        "{%0,%1,%2,%3},{%4,%5,%6,%7},{%8,%9},{%0,%1,%2,%3};"
        : "+f"(d[0]), "+f"(d[1]), "+f"(d[2]), "+f"(d[3])
        : "r"(a[0]), "r"(a[1]), "r"(a[2]), "r"(a[3]), "r"(b[0]), "r"(b[1]));
}
__device__ __forceinline__ unsigned packh2(float a, float b) {
    __half2 hv = __floats2half2_rn(a, b);
    return *(unsigned*)&hv;
}

// ---------------------------------------------------------------------------
// fp32 -> fp16 convert for all three inputs in ONE launch
// ---------------------------------------------------------------------------
__global__ __launch_bounds__(256) void tofp16_all(
    const float4* __restrict__ x,  uint2* __restrict__ xf,  int n1,
    const float4* __restrict__ wq, uint2* __restrict__ wqf, int n2,
    const float4* __restrict__ wo, uint2* __restrict__ wof, int n3)
{
    int i = blockIdx.x * blockDim.x + threadIdx.x;
    const float4* src; uint2* dst; int j;
    if (i < n1)                { src = x;  dst = xf;  j = i; }
    else if (i < n1 + n2)      { src = wq; dst = wqf; j = i - n1; }
    else if (i < n1 + n2 + n3) { src = wo; dst = wof; j = i - n1 - n2; }
    else return;
    float4 v = src[j];
    uint2 o;
    o.x = packh2(v.x, v.y);
    o.y = packh2(v.z, v.w);
    dst[j] = o;
}

// ---------------------------------------------------------------------------
// Tensor-core fp16 GEMM (unchanged from R12/R15 best): CTA 128x128, GBK=32,
// 3-stage ring, one __syncthreads per iteration, 2 CTAs/SM.
// ---------------------------------------------------------------------------
#define GBM 128
#define GBN 128
#define GBK 32
#define APITCH 40
#define BPITCH 136
#define ASZ (128*APITCH)
#define BSZ (32*BPITCH)
#define NSTG 3
#define GEMM_SMEM (NSTG*(ASZ + BSZ)*2)

template<int OMODE>
__global__ __launch_bounds__(128, 2) void gemm_f16(
    const __half* __restrict__ A, const __half* __restrict__ B,
    const float* __restrict__ bias,
    float* __restrict__ C, __half* __restrict__ Cf,
    int M, int N, int K)
{
    extern __shared__ char smem[];
    __half* sA = (__half*)smem;
    __half* sB = sA + NSTG * ASZ;

    const int tid  = threadIdx.x;
    const int lane = tid & 31;
    const int warp = tid >> 5;
    const int bm   = blockIdx.y * GBM;
    const int bn   = blockIdx.x * GBN;
    const int wm   = (warp & 1) * 64;
    const int wn   = (warp >> 1) * 64;

    float acc[4][8][4];
#pragma unroll
    for (int mi = 0; mi < 4; mi++)
#pragma unroll
        for (int n = 0; n < 8; n++)
#pragma unroll
            for (int e = 0; e < 4; e++) acc[mi][n][e] = 0.f;

    const int NIT = K / GBK;
    auto prefetch = [&](int stg, int it) {
        if (it < NIT) {
            const int k0 = it * GBK;
            const __half* a = A + (size_t)bm * K + k0;
#pragma unroll
            for (int i = 0; i < 4; i++) {
                int idx = tid + i * 128;
                int r = idx >> 2, c = (idx & 3) * 8;
                cpa16(sptr(&sA[stg * ASZ + r * APITCH + c]), a + (size_t)r * K + c);
            }
            const __half* b = B + (size_t)k0 * N + bn;
#pragma unroll
            for (int i = 0; i < 4; i++) {
                int idx = tid + i * 128;
                int r = idx >> 4, c = (idx & 15) * 8;
                cpa16(sptr(&sB[stg * BSZ + r * BPITCH + c]), b + (size_t)r * N + c);
            }
        }
        asm volatile("cp.async.commit_group;");
    };

    prefetch(0, 0);
    prefetch(1, 1);
    int st = 0;
    for (int it = 0; it < NIT; it++) {
        asm volatile("cp.async.wait_group 1;");
        __syncthreads();
        int nxt = st + 2; if (nxt >= NSTG) nxt -= NSTG;
        prefetch(nxt, it + 2);

#pragma unroll
        for (int kk = 0; kk < GBK; kk += 16) {
            unsigned af[4][4], bf[4][4];
#pragma unroll
            for (int mi = 0; mi < 4; mi++) {
                int row = wm + mi * 16 + (lane & 15);
                int col = kk + (lane >> 4) * 8;
                ldsm4(af[mi], sptr(&sA[st * ASZ + row * APITCH + col]));
            }
#pragma unroll
            for (int nj = 0; nj < 4; nj++) {
                int row = kk + (lane & 15);
                int col = wn + nj * 16 + (lane >> 4) * 8;
                ldsm4t(bf[nj], sptr(&sB[st * BSZ + row * BPITCH + col]));
            }
#pragma unroll
            for (int mi = 0; mi < 4; mi++)
#pragma unroll
                for (int nj = 0; nj < 4; nj++)
#pragma unroll
                    for (int sub = 0; sub < 2; sub++)
                        mma16816h(acc[mi][nj * 2 + sub], af[mi], &bf[nj][sub * 2]);
        }
        if (++st >= NSTG) st = 0;
    }

#pragma unroll
    for (int mi = 0; mi < 4; mi++) {
        int r0 = bm + wm + mi * 16 + (lane >> 2);
#pragma unroll
        for (int n = 0; n < 8; n++) {
            int c0 = bn + wn + n * 8 + (lane & 3) * 2;
            float2 bv = *(const float2*)(bias + c0);
            float v00 = acc[mi][n][0] + bv.x, v01 = acc[mi][n][1] + bv.y;
            float v10 = acc[mi][n][2] + bv.x, v11 = acc[mi][n][3] + bv.y;
            if (OMODE == 0) {
                *(float2*)(C + (size_t)r0 * N + c0) = make_float2(v00, v01);
                *(float2*)(C + (size_t)(r0 + 8) * N + c0) = make_float2(v10, v11);
            } else {
                *(unsigned*)(Cf + (size_t)r0 * N + c0) = packh2(v00, v01);
                *(unsigned*)(Cf + (size_t)(r0 + 8) * N + c0) = packh2(v10, v11);
            }
        }
    }
}

// ---------------------------------------------------------------------------
// Flash attention: 128 threads, 4 warps x 32 q rows, fp16 MMA, log2-domain
// softmax with PRE-SCALED Q (no per-score scale) and integer-quantized max
// (warp-uniform rescale skip). 3-stage K/V ring, 2 CTAs/SM.
// ---------------------------------------------------------------------------
#define KPH 72
#define TSZH (64*KPH)
#define STGH (2*TSZH)
#define FLASH_SMEM (NSTG*STGH*2)   // 55296 bytes
#define SCALE_L2E 0.1803368801f    // 0.125 * log2(e)

__global__ __launch_bounds__(128, 2) void flash_attn_mma(
    const __half* __restrict__ qkv, __half* __restrict__ outf)
{
    extern __shared__ char smraw[];
    __half* sm = (__half*)smraw;

    const int tid  = threadIdx.x;
    const int lane = tid & 31;
    const int warp = tid >> 5;                      // 0..3
    const int bh   = blockIdx.y;
    const int b    = bh >> 4;
    const int h    = bh & (NHEAD - 1);
    const int qb   = (gridDim.x - 1) - blockIdx.x;  // heavy tiles first
    const int q0   = qb * 128;
    const int wm   = warp * 32;                     // 32 q rows per warp
    const int r    = lane >> 2;
    const int cp   = (lane & 3) * 2;

    // ---- Q fragments, PRE-SCALED by 0.125*log2(e) in fp16 ----
    const __half2 qsc = __float2half2_rn(SCALE_L2E);
    unsigned qf[4][2][4];
#pragma unroll
    for (int mi = 0; mi < 2; mi++) {
        const size_t base  = ((size_t)(b * SEQ) + q0 + wm + mi * 16 + r) * QKV_N + h * HDIM;
        const size_t base8 = base + (size_t)8 * QKV_N;
#pragma unroll
        for (int kk = 0; kk < 4; kk++) {
            int c0 = kk * 16 + cp;
            unsigned raw[4];
            raw[0] = *(const unsigned*)(qkv + base  + c0);
            raw[1] = *(const unsigned*)(qkv + base8 + c0);
            raw[2] = *(const unsigned*)(qkv + base  + c0 + 8);
            raw[3] = *(const unsigned*)(qkv + base8 + c0 + 8);
#pragma unroll
            for (int j = 0; j < 4; j++) {
                __half2 v = __hmul2(*(__half2*)&raw[j], qsc);
                qf[kk][mi][j] = *(unsigned*)&v;
            }
        }
    }

    float m[4] = {-1e30f, -1e30f, -1e30f, -1e30f};  // [mi*2 + (0:r,1:r+8)]
    float l[4] = {0.f, 0.f, 0.f, 0.f};
    float o[2][8][4];
#pragma unroll
    for (int mi = 0; mi < 2; mi++)
#pragma unroll
        for (int nf = 0; nf < 8; nf++)
#pragma unroll
            for (int e = 0; e < 4; e++) o[mi][nf][e] = 0.f;

    const size_t koff = (size_t)EMBD + h * HDIM;
    const size_t voff = (size_t)(2 * EMBD) + h * HDIM;

    const int ntiles = 2 * qb + 2;
    auto prefetch = [&](int stg, int t) {
        if (t < ntiles) {
            const int k0 = t * 64;
#pragma unroll
            for (int i = 0; i < 8; i++) {
                int id = tid + i * 128;           // 0..1023
                int tt = id >> 9;                 // 0:K 1:V
                int rr = (id >> 3) & 63;
                int cc = (id & 7) * 8;
                const __half* src = qkv + ((size_t)(b * SEQ) + k0 + rr) * QKV_N
                                  + (tt ? voff : koff) + cc;
                cpa16(sptr(&sm[stg * STGH + tt * TSZH + rr * KPH + cc]), src);
            }
        }
        asm volatile("cp.async.commit_group;");
    };

    prefetch(0, 0);
    prefetch(1, 1);
    int st = 0;
    for (int t = 0; t < ntiles; t++) {
        const int k0 = t * 64;
        asm volatile("cp.async.wait_group 1;");
        __syncthreads();
        int nxt = st + 2; if (nxt >= NSTG) nxt -= NSTG;
        prefetch(nxt, t + 2);

        if (k0 <= q0 + wm + 31) {   // causal warp-level skip
            const __half* Kf = sm + st * STGH;
            const __half* Vf = sm + st * STGH + TSZH;

            // ---- S = (Q*scale) K^T  (already in log2 units) ----
            float s[2][8][4];
#pragma unroll
            for (int mi = 0; mi < 2; mi++)
#pragma unroll
                for (int nf = 0; nf < 8; nf++)
#pragma unroll
                    for (int e = 0; e < 4; e++) s[mi][nf][e] = 0.f;

#pragma unroll
            for (int kk = 0; kk < 4; kk++) {
#pragma unroll
                for (int g = 0; g < 4; g++) {
                    unsigned kf4[4];
                    int off = (16 * g + (lane & 15)) * KPH + kk * 16 + (lane >> 4) * 8;
                    ldsm4(kf4, sptr(Kf + off));
                    unsigned b0[2] = {kf4[0], kf4[2]}, b1[2] = {kf4[1], kf4[3]};
#pragma unroll
                    for (int mi = 0; mi < 2; mi++) {
                        mma16816h(s[mi][2*g],     qf[kk][mi], b0);
                        mma16816h(s[mi][2*g + 1], qf[kk][mi], b1);
                    }
                }
            }

            // ---- masking + online softmax (quantized max, log2 domain) ----
            unsigned pf[2][8][2];
#pragma unroll
            for (int mi = 0; mi < 2; mi++) {
                const int qrow = q0 + wm + mi * 16 + r;
                const bool need_mask = (k0 + 63) > (q0 + wm + mi * 16);
                float mx0 = -1e30f, mx1 = -1e30f;
#pragma unroll
                for (int nf = 0; nf < 8; nf++) {
                    if (need_mask) {
                        int c0 = k0 + nf * 8 + cp;
                        if (c0     > qrow)     s[mi][nf][0] = -1e30f;
                        if (c0 + 1 > qrow)     s[mi][nf][1] = -1e30f;
                        if (c0     > qrow + 8) s[mi][nf][2] = -1e30f;
                        if (c0 + 1 > qrow + 8) s[mi][nf][3] = -1e30f;
                    }
                    mx0 = fmaxf(mx0, fmaxf(s[mi][nf][0], s[mi][nf][1]));
                    mx1 = fmaxf(mx1, fmaxf(s[mi][nf][2], s[mi][nf][3]));
                }
                mx0 = fmaxf(mx0, __shfl_xor_sync(0xffffffffu, mx0, 1));
                mx0 = fmaxf(mx0, __shfl_xor_sync(0xffffffffu, mx0, 2));
                mx1 = fmaxf(mx1, __shfl_xor_sync(0xffffffffu, mx1, 1));
                mx1 = fmaxf(mx1, __shfl_xor_sync(0xffffffffu, mx1, 2));

                const float om0 = m[2*mi], om1 = m[2*mi+1];
                const float nm0 = fmaxf(om0, ceilf(mx0));
                const float nm1 = fmaxf(om1, ceilf(mx1));
                // Warp-uniform skip: if no row in this warp raised its
                // quantized max, the rescale is exactly a no-op.
                if (!__all_sync(0xffffffffu, (nm0 == om0) && (nm1 == om1))) {
                    const float cr0 = exp2f(om0 - nm0), cr1 = exp2f(om1 - nm1);
                    m[2*mi] = nm0; m[2*mi+1] = nm1;
                    l[2*mi] *= cr0; l[2*mi+1] *= cr1;
#pragma unroll
                    for (int nf = 0; nf < 8; nf++) {
                        o[mi][nf][0] *= cr0; o[mi][nf][1] *= cr0;
                        o[mi][nf][2] *= cr1; o[mi][nf][3] *= cr1;
                    }
                }
#pragma unroll
                for (int nf = 0; nf < 8; nf++) {
                    float p0 = exp2f(s[mi][nf][0] - nm0);
                    float p1 = exp2f(s[mi][nf][1] - nm0);
                    float p2 = exp2f(s[mi][nf][2] - nm1);
                    float p3 = exp2f(s[mi][nf][3] - nm1);
                    l[2*mi]   += p0 + p1;
                    l[2*mi+1] += p2 + p3;
                    pf[mi][nf][0] = packh2(p0, p1);
                    pf[mi][nf][1] = packh2(p2, p3);
                }
            }

            // ---- O += P V ----
#pragma unroll
            for (int kp = 0; kp < 4; kp++) {
                unsigned pa0[4] = {pf[0][2*kp][0], pf[0][2*kp][1], pf[0][2*kp+1][0], pf[0][2*kp+1][1]};
                unsigned pa1[4] = {pf[1][2*kp][0], pf[1][2*kp][1], pf[1][2*kp+1][0], pf[1][2*kp+1][1]};
#pragma unroll
                for (int dg = 0; dg < 4; dg++) {
                    unsigned vf4[4];
                    int off = (kp * 16 + (lane & 15)) * KPH + dg * 16 + (lane >> 4) * 8;
                    ldsm4t(vf4, sptr(Vf + off));
                    mma16816h(o[0][2*dg],     pa0, &vf4[0]);
                    mma16816h(o[0][2*dg + 1], pa0, &vf4[2]);
                    mma16816h(o[1][2*dg],     pa1, &vf4[0]);
                    mma16816h(o[1][2*dg + 1], pa1, &vf4[2]);
                }
            }
        }
        if (++st >= NSTG) st = 0;
    }

    // ---- finalize: quad-reduce l, normalize, store fp16 ----
#pragma unroll
    for (int i = 0; i < 4; i++) {
        l[i] += __shfl_xor_sync(0xffffffffu, l[i], 1);
        l[i] += __shfl_xor_sync(0xffffffffu, l[i], 2);
    }
#pragma unroll
    for (int mi = 0; mi < 2; mi++) {
        const float inv0 = 1.f / l[2*mi], inv1 = 1.f / l[2*mi+1];
        const size_t obase  = ((size_t)(b * SEQ) + q0 + wm + mi * 16 + r) * EMBD + h * HDIM;
        const size_t obase8 = obase + (size_t)8 * EMBD;
#pragma unroll
        for (int nf = 0; nf < 8; nf++) {
            int c0 = nf * 8 + cp;
            *(unsigned*)(outf + obase  + c0) = packh2(o[mi][nf][0] * inv0, o[mi][nf][1] * inv0);
            *(unsigned*)(outf + obase8 + c0) = packh2(o[mi][nf][2] * inv1, o[mi][nf][3] * inv1);
        }
    }
}

// ---------------------------------------------------------------------------
// Launch
// ---------------------------------------------------------------------------
extern "C" void kernel_launch(void* const* d_in, const int* in_sizes, int n_in,
                              void* d_out, int out_size)
{
    const float* x     = (const float*)d_in[0];
    const float* W_qkv = (const float*)d_in[1];
    const float* b_qkv = (const float*)d_in[2];
    const float* W_out = (const float*)d_in[3];
    const float* b_out = (const float*)d_in[4];
    float* out = (float*)d_out;

    __half *xf, *wqf, *wof, *qkvf, *af;
    cudaGetSymbolAddress((void**)&xf,   g_xf);
    cudaGetSymbolAddress((void**)&wqf,  g_wqf);
    cudaGetSymbolAddress((void**)&wof,  g_wof);
    cudaGetSymbolAddress((void**)&qkvf, g_qkvf);
    cudaGetSymbolAddress((void**)&af,   g_af);

    const int M = BATCH * SEQ;                       // 8192

    cudaFuncSetAttribute(gemm_f16<0>, cudaFuncAttributeMaxDynamicSharedMemorySize, GEMM_SMEM);
    cudaFuncSetAttribute(gemm_f16<2>, cudaFuncAttributeMaxDynamicSharedMemorySize, GEMM_SMEM);
    cudaFuncSetAttribute(flash_attn_mma, cudaFuncAttributeMaxDynamicSharedMemorySize, FLASH_SMEM);

    // 1) convert all inputs to fp16 in one launch
    {
        int n1 = M * EMBD / 4;          // 2097152
        int n2 = EMBD * QKV_N / 4;      //  786432
        int n3 = EMBD * EMBD / 4;       //  262144
        int nt = n1 + n2 + n3;
        tofp16_all<<<(nt + 255) / 256, 256>>>(
            (const float4*)x, (uint2*)xf, n1,
            (const float4*)W_qkv, (uint2*)wqf, n2,
            (const float4*)W_out, (uint2*)wof, n3);
    }
    // 2) QKV projection (fp16, fp32 accumulate) -> fp16 qkv
    {
        dim3 grid(QKV_N / GBN, M / GBM);
        gemm_f16<2><<<grid, 128, GEMM_SMEM>>>(xf, wqf, b_qkv, nullptr, qkvf, M, QKV_N, EMBD);
    }
    // 3) Flash attention (fp16 MMA, 4 warps x 32 rows) -> fp16 attn output
    {
        dim3 grid(SEQ / 128, BATCH * NHEAD);
        flash_attn_mma<<<grid, 128, FLASH_SMEM>>>(qkvf, af);
    }
    // 4) Output projection (fp16, fp32 accumulate) -> fp32 result
    {
        dim3 grid(EMBD / GBN, M / GBM);
        gemm_f16<0><<<grid, 128, GEMM_SMEM>>>(af, wof, b_out, out, nullptr, M, EMBD, EMBD);
    }
}